// round 5
// baseline (speedup 1.0000x reference)
#include <cuda_runtime.h>
#include <math.h>

#define NN  131072
#define GG  1024
#define NPG 128
#define EE  2097152
#define HH  64
#define KK  30
#define DD  193
#define CAP 3072
#define SXC 196   // xc row stride (multiple of 4)

// ---------------- scratch (static device globals; no allocation) ----------------
__device__ int g_deg[NN];
__device__ int g_cur[NN];
__device__ int g_noff[NN];      // within-graph exclusive offsets
__device__ int g_gtot[GG];      // per-graph edge totals
__device__ int g_gbase[GG];     // per-graph base into g_esrc
__device__ unsigned char g_esrc[EE];

// ---------------- preprocessing (5 kernels; k_main is kernel #6) ----------------
__global__ void k_zero() {
    int i = blockIdx.x * blockDim.x + threadIdx.x;
    g_deg[i] = 0; g_cur[i] = 0;
}

__global__ void k_count(const int* __restrict__ dst) {
    int e = blockIdx.x * blockDim.x + threadIdx.x;
    if (e < EE) atomicAdd(&g_deg[dst[e]], 1);
}

__global__ void k_noff2() {   // per-graph: local exclusive scan of degrees + total
    int g = blockIdx.x, i = threadIdx.x;
    int lane = i & 31, w = i >> 5;
    int v = g_deg[g * NPG + i];
    int x = v;
    for (int o = 1; o < 32; o <<= 1) {
        int t = __shfl_up_sync(0xffffffffu, x, o);
        if (lane >= o) x += t;
    }
    __shared__ int ws[4], wb[4];
    if (lane == 31) ws[w] = x;
    __syncthreads();
    if (i == 0) {
        int a = 0;
        for (int q = 0; q < 4; q++) { wb[q] = a; a += ws[q]; }
        g_gtot[g] = a;
    }
    __syncthreads();
    g_noff[g * NPG + i] = wb[w] + x - v;
}

__global__ void k_gscan() {   // exclusive scan of graph totals -> bases
    __shared__ int s[GG];
    int t = threadIdx.x;
    int v = g_gtot[t];
    s[t] = v;
    __syncthreads();
    for (int o = 1; o < GG; o <<= 1) {
        int a = (t >= o) ? s[t - o] : 0;
        __syncthreads();
        s[t] += a;
        __syncthreads();
    }
    g_gbase[t] = s[t] - v;
}

__global__ void k_scatter(const int* __restrict__ src, const int* __restrict__ dst) {
    int e = blockIdx.x * blockDim.x + threadIdx.x;
    if (e < EE) {
        int d = dst[e];
        int pos = g_gbase[d >> 7] + g_noff[d] + atomicAdd(&g_cur[d], 1);
        g_esrc[pos] = (unsigned char)(src[e] & 127);
    }
}

// ---------------- main fused per-graph kernel ----------------
struct SmemD {
    float xc[NPG * SXC];   // concat(x1,x2,x3,x4); cols 128..191 stage embedding pre-L3
    float h2t[64 * 129];   // (h @ W)*dinv, CHANNEL-major, stride 129 (odd, conflict-free)
    float Wsh[4096];       // weight staging (reused for conv1_w / conv2_w)
    float dinv[NPG];
    float keyv[NPG];
    float bsh[64];         // bias (or W3)
    float h4t[NPG];
    float partial[1024];
    float h1c[16 * KK];
    float pool[16 * 16];
    float c2o[352];
    float hm[128];
    int   noff[NPG + 1];   // LOCAL offsets (noff[128] = edge count)
    int   sel[KK];
    unsigned char esrc[CAP];
};

#define NT 1024

__global__ __launch_bounds__(NT, 1) void k_main(
    const int* __restrict__ z, const float* __restrict__ z_table,
    const float* __restrict__ W0, const float* __restrict__ b0,
    const float* __restrict__ W1, const float* __restrict__ b1,
    const float* __restrict__ W2, const float* __restrict__ b2,
    const float* __restrict__ W3, const float* __restrict__ b3,
    const float* __restrict__ c1w, const float* __restrict__ c1b,
    const float* __restrict__ c2w, const float* __restrict__ c2b,
    const float* __restrict__ l1w, const float* __restrict__ l1b,
    const float* __restrict__ l2w, const float* __restrict__ l2b,
    float* __restrict__ out)
{
    extern __shared__ unsigned char smraw[];
    SmemD& s = *reinterpret_cast<SmemD*>(smraw);
    const int tid = threadIdx.x;
    const int g = blockIdx.x;
    const int nb = g * NPG;
    const int gbase = __ldg(&g_gbase[g]);

    // ---- init: local offsets, degrees, edge copy, embedding (into xc cols 128..191) ----
    if (tid < NPG) s.noff[tid] = g_noff[nb + tid];
    else if (tid == NPG) s.noff[NPG] = g_gtot[g];
    __syncthreads();
    const int cnt = s.noff[NPG];
    const bool inS = (cnt <= CAP);

    if (tid < NPG) {
        int dl = s.noff[tid + 1] - s.noff[tid];
        s.dinv[tid] = rsqrtf((float)(dl + 1));   // +1 self loop
    }
    if (inS) {
        for (int i = tid; i < cnt; i += NT) s.esrc[i] = g_esrc[gbase + i];
    }
    for (int idx = tid; idx < NPG * 16; idx += NT) {
        int n = idx >> 4, q = idx & 15;
        float4 v = *reinterpret_cast<const float4*>(&z_table[__ldg(&z[nb + n]) * 64 + 4 * q]);
        *reinterpret_cast<float4*>(&s.xc[n * SXC + 128 + 4 * q]) = v;
    }
    __syncthreads();

    // ---- GEMM: h2t[c][r] = (xin @ W)[r][c] * dinv[r]  (2 rows x 4 cols / thread) ----
    auto gemm = [&](const float* xin, const float* Wg) {
        for (int i = tid; i < 1024; i += NT)
            *reinterpret_cast<float4*>(&s.Wsh[4 * i]) =
                *reinterpret_cast<const float4*>(&Wg[4 * i]);
        __syncthreads();
        const int c0 = (tid & 15) * 4;     // 4 contiguous cols
        const int r0 = (tid >> 4) * 2;     // 2 rows
        float acc[2][4];
        #pragma unroll
        for (int i = 0; i < 2; i++)
            #pragma unroll
            for (int j = 0; j < 4; j++) acc[i][j] = 0.f;
        #pragma unroll 4
        for (int kk = 0; kk < 16; kk++) {
            float4 xv[2];
            #pragma unroll
            for (int i = 0; i < 2; i++)
                xv[i] = *reinterpret_cast<const float4*>(&xin[(r0 + i) * SXC + 4 * kk]);
            #pragma unroll
            for (int kq = 0; kq < 4; kq++) {
                float4 wv = *reinterpret_cast<const float4*>(&s.Wsh[(4 * kk + kq) * 64 + c0]);
                float xs[2] = { (&xv[0].x)[kq], (&xv[1].x)[kq] };
                #pragma unroll
                for (int i = 0; i < 2; i++) {
                    acc[i][0] += xs[i] * wv.x;
                    acc[i][1] += xs[i] * wv.y;
                    acc[i][2] += xs[i] * wv.z;
                    acc[i][3] += xs[i] * wv.w;
                }
            }
        }
        #pragma unroll
        for (int i = 0; i < 2; i++) {
            float dv = s.dinv[r0 + i];
            #pragma unroll
            for (int j = 0; j < 4; j++)
                s.h2t[(c0 + j) * 129 + r0 + i] = acc[i][j] * dv;
        }
        __syncthreads();
    };

    // ---- gather + tanh: c = tid&63, 8 dst per thread ----
    auto gather = [&](int outbase) {
        const int c = tid & 63;
        const int dg = tid >> 6;           // 0..15, 8 dst each
        const float* hr = &s.h2t[c * 129];
        const float bc = s.bsh[c];
        #pragma unroll 2
        for (int dd = 0; dd < 8; dd++) {
            int d = dg * 8 + dd;
            float sum = hr[d];                      // self loop
            int e0 = s.noff[d], e1 = s.noff[d + 1];
            int e = e0;
            if (inS) {
                for (; e + 4 <= e1; e += 4) {
                    int a0 = s.esrc[e], a1 = s.esrc[e + 1];
                    int a2 = s.esrc[e + 2], a3 = s.esrc[e + 3];
                    sum += hr[a0] + hr[a1] + hr[a2] + hr[a3];
                }
                for (; e < e1; e++) sum += hr[s.esrc[e]];
            } else {
                for (; e < e1; e++) sum += hr[g_esrc[gbase + e]];
            }
            s.xc[d * SXC + outbase + c] = tanhf(s.dinv[d] * sum + bc);
        }
        __syncthreads();
    };

    if (tid < 64) s.bsh[tid] = b0[tid];
    gemm(&s.xc[128], W0);       gather(0);    // layer 1: input = staged embedding
    if (tid < 64) s.bsh[tid] = b1[tid];
    gemm(&s.xc[0], W1);         gather(64);
    if (tid < 64) s.bsh[tid] = b2[tid];
    gemm(&s.xc[64], W2);        gather(128);  // overwrites embedding staging (done with it)

    // ---- layer 4: 64 -> 1 ----
    if (tid < 64) s.bsh[tid] = W3[tid];
    __syncthreads();
    if (tid < 128) {
        float sum = 0.f;
        #pragma unroll
        for (int kq = 0; kq < 16; kq++) {
            float4 xv = *reinterpret_cast<const float4*>(&s.xc[tid * SXC + 128 + 4 * kq]);
            sum += xv.x * s.bsh[4 * kq] + xv.y * s.bsh[4 * kq + 1]
                 + xv.z * s.bsh[4 * kq + 2] + xv.w * s.bsh[4 * kq + 3];
        }
        s.h4t[tid] = sum * s.dinv[tid];
    }
    __syncthreads();
    if (tid < 128) {
        int d = tid;
        float sum = s.h4t[d];
        int e0 = s.noff[d], e1 = s.noff[d + 1];
        if (inS) {
            int e = e0;
            for (; e + 4 <= e1; e += 4) {
                int a0 = s.esrc[e], a1 = s.esrc[e + 1];
                int a2 = s.esrc[e + 2], a3 = s.esrc[e + 3];
                sum += s.h4t[a0] + s.h4t[a1] + s.h4t[a2] + s.h4t[a3];
            }
            for (; e < e1; e++) sum += s.h4t[s.esrc[e]];
        } else {
            for (int e = e0; e < e1; e++) sum += s.h4t[g_esrc[gbase + e]];
        }
        float v = tanhf(s.dinv[d] * sum + b3[0]);
        s.keyv[d] = v;
        s.xc[d * SXC + 192] = v;
    }
    __syncthreads();

    // ---- sort-pool: stable descending rank; keep top KK ----
    if (tid < 128) {
        float ki = s.keyv[tid];
        int r = 0;
        for (int j = 0; j < 128; j++) {
            float kj = s.keyv[j];
            r += (kj > ki) || (kj == ki && j < tid);
        }
        if (r < KK) s.sel[r] = tid;
    }
    __syncthreads();

    // ---- conv1: per-node linear D->16, relu ----
    for (int i = tid; i < 16 * DD; i += NT) s.Wsh[i] = c1w[i];
    __syncthreads();
    if (tid < 16 * KK) {
        int c = tid & 15, k2 = tid >> 4;
        const float* row = &s.xc[s.sel[k2] * SXC];
        const float* wr = &s.Wsh[c * DD];
        float sum = __ldg(&c1b[c]);
        for (int d2 = 0; d2 < DD; d2++) sum += row[d2] * wr[d2];
        s.h1c[c * KK + k2] = fmaxf(sum, 0.f);
    }
    __syncthreads();

    // ---- maxpool(2,2) + stage conv2_w ----
    if (tid < 240) {
        int c = tid / 15, t2 = tid % 15;
        s.pool[c * 16 + t2] = fmaxf(s.h1c[c * KK + 2 * t2], s.h1c[c * KK + 2 * t2 + 1]);
    }
    for (int i = tid; i < 2560; i += NT) s.Wsh[i] = c2w[i];
    __syncthreads();

    // ---- conv2: 16ch x len15, k=5 -> 32ch x len11, relu ----
    if (tid < 352) {
        int o = tid / 11, t2 = tid % 11;
        float sum = __ldg(&c2b[o]);
        const float* wr = &s.Wsh[o * 80];
        #pragma unroll
        for (int i3 = 0; i3 < 16; i3++)
            #pragma unroll
            for (int j3 = 0; j3 < 5; j3++)
                sum += s.pool[i3 * 16 + t2 + j3] * wr[i3 * 5 + j3];
        s.c2o[tid] = fmaxf(sum, 0.f);
    }
    __syncthreads();

    // ---- lin1 (352->128, relu), 8-way f-split ----
    {
        int m = tid & 127, q = tid >> 7;    // q in 0..7
        int f0 = q * 44;
        float sum = 0.f;
        for (int f = f0; f < f0 + 44; f++) sum += s.c2o[f] * __ldg(&l1w[f * 128 + m]);
        s.partial[tid] = sum;
    }
    __syncthreads();
    if (tid < 128) {
        float acc = __ldg(&l1b[tid]);
        #pragma unroll
        for (int q = 0; q < 8; q++) acc += s.partial[tid + 128 * q];
        s.hm[tid] = fmaxf(acc, 0.f);
    }
    __syncthreads();

    // ---- lin2 (128->1) ----
    if (tid < 32) {
        float sum = 0.f;
        #pragma unroll
        for (int q = 0; q < 4; q++) {
            int m = tid + 32 * q;
            sum += s.hm[m] * __ldg(&l2w[m]);
        }
        for (int o = 16; o; o >>= 1) sum += __shfl_down_sync(0xffffffffu, sum, o);
        if (tid == 0) out[g] = sum + __ldg(&l2b[0]);
    }
}

// ---------------- launch ----------------
extern "C" void kernel_launch(void* const* d_in, const int* in_sizes, int n_in,
                              void* d_out, int out_size) {
    const int*   z   = (const int*)d_in[0];
    const int*   ei  = (const int*)d_in[1];
    const float* zt  = (const float*)d_in[3];
    const float* W0  = (const float*)d_in[4];
    const float* b0  = (const float*)d_in[5];
    const float* W1  = (const float*)d_in[6];
    const float* b1  = (const float*)d_in[7];
    const float* W2  = (const float*)d_in[8];
    const float* b2  = (const float*)d_in[9];
    const float* W3  = (const float*)d_in[10];
    const float* b3  = (const float*)d_in[11];
    const float* c1w = (const float*)d_in[12];
    const float* c1b = (const float*)d_in[13];
    const float* c2w = (const float*)d_in[14];
    const float* c2b = (const float*)d_in[15];
    const float* l1w = (const float*)d_in[16];
    const float* l1b = (const float*)d_in[17];
    const float* l2w = (const float*)d_in[18];
    const float* l2b = (const float*)d_in[19];
    float* out = (float*)d_out;

    const int* src = ei;
    const int* dst = ei + EE;

    // exactly 6 kernel launches: k_main is kernel #6
    k_zero<<<NN / 256, 256>>>();
    k_count<<<EE / 256, 256>>>(dst);
    k_noff2<<<GG, 128>>>();
    k_gscan<<<1, GG>>>();
    k_scatter<<<EE / 256, 256>>>(src, dst);

    static_assert(sizeof(SmemD) <= 232448, "smem too large");
    cudaFuncSetAttribute(k_main, cudaFuncAttributeMaxDynamicSharedMemorySize,
                         (int)sizeof(SmemD));
    k_main<<<GG, NT, sizeof(SmemD)>>>(z, zt, W0, b0, W1, b1, W2, b2, W3, b3,
                                      c1w, c1b, c2w, c2b, l1w, l1b, l2w, l2b, out);
}

// round 6
// speedup vs baseline: 1.5816x; 1.5816x over previous
#include <cuda_runtime.h>
#include <math.h>

#define NN    131072
#define GG    1024
#define NPG   128
#define EE    2097152
#define HH    64
#define KK    30
#define DD    193
#define CAP   4096
#define SLOT  8192          // per-graph padded edge slot (bytes), 4-aligned
#define SXC   196           // xc row stride (multiple of 4)

// ---------------- scratch (static device globals; zero-initialized) ----------------
__device__ int g_deg[NN];                 // real in-degree (zeroed by k_main tail)
__device__ int g_cur[NN];                 // scatter cursors (zeroed by k_main tail)
__device__ int g_noff[NN + GG];           // padded local offsets; [NN+g] = padded total
__device__ unsigned char g_esrc[GG * SLOT];

// ---------------- preprocessing (3 kernels; k_main is the 4th launch) -------------
__global__ void k_count(const int* __restrict__ dst) {
    int e = blockIdx.x * blockDim.x + threadIdx.x;
    if (e < EE) atomicAdd(&g_deg[dst[e]], 1);
}

__global__ void k_noff2() {   // per-graph scan of PADDED degrees + sentinel fill
    int g = blockIdx.x, i = threadIdx.x;
    int lane = i & 31, w = i >> 5;
    int deg = g_deg[g * NPG + i];
    int pdeg = (deg + 3) & ~3;
    int x = pdeg;
    for (int o = 1; o < 32; o <<= 1) {
        int t = __shfl_up_sync(0xffffffffu, x, o);
        if (lane >= o) x += t;
    }
    __shared__ int ws[4], wb[4];
    if (lane == 31) ws[w] = x;
    __syncthreads();
    if (i == 0) {
        int a = 0;
        for (int q = 0; q < 4; q++) { wb[q] = a; a += ws[q]; }
        g_noff[NN + g] = a;               // padded total
    }
    __syncthreads();
    int off = wb[w] + x - pdeg;           // exclusive padded offset
    g_noff[g * NPG + i] = off;
    // write pad sentinels (index 128 -> h2t row 128 == 0)
    unsigned char* slot = &g_esrc[g * SLOT];
    for (int q = deg; q < pdeg; q++) slot[off + q] = 128;
}

__global__ void k_scatter(const int* __restrict__ src, const int* __restrict__ dst) {
    int e = blockIdx.x * blockDim.x + threadIdx.x;
    if (e < EE) {
        int d = dst[e];
        int pos = g_noff[d] + atomicAdd(&g_cur[d], 1);
        g_esrc[(d >> 7) * SLOT + pos] = (unsigned char)(src[e] & 127);
    }
}

// ---------------- main fused per-graph kernel ----------------
struct SmemD {
    float xc[NPG * SXC];   // concat(x1,x2,x3,x4); cols 128..191 stage embedding pre-L3
    float h2t[64 * 129];   // (h @ W)*dinv, CHANNEL-major, stride 129; row 128 == 0 (pad sink)
    float Wsh[4096];       // weight staging (reused for conv1_w / conv2_w)
    float dinv[NPG];
    float keyv[NPG];
    float bsh[64];         // bias (or W3)
    float h4t[132];        // [128] == 0 (pad sink)
    float partial[512];
    float h1c[16 * KK];
    float pool[16 * 16];
    float c2o[352];
    float hm[128];
    int   noff[NPG + 1];   // padded LOCAL offsets; noff[128] = padded count
    int   sel[KK];
    unsigned char esrc[CAP];   // 4-aligned (follows int members)
};

#define NT 512

__global__ __launch_bounds__(NT, 1) void k_main(
    const int* __restrict__ z, const float* __restrict__ z_table,
    const float* __restrict__ W0, const float* __restrict__ b0,
    const float* __restrict__ W1, const float* __restrict__ b1,
    const float* __restrict__ W2, const float* __restrict__ b2,
    const float* __restrict__ W3, const float* __restrict__ b3,
    const float* __restrict__ c1w, const float* __restrict__ c1b,
    const float* __restrict__ c2w, const float* __restrict__ c2b,
    const float* __restrict__ l1w, const float* __restrict__ l1b,
    const float* __restrict__ l2w, const float* __restrict__ l2b,
    float* __restrict__ out)
{
    extern __shared__ unsigned char smraw[];
    SmemD& s = *reinterpret_cast<SmemD*>(smraw);
    const int tid = threadIdx.x;
    const int g = blockIdx.x;
    const int nb = g * NPG;

    // ---- init: offsets, degrees, pad sinks, edge copy, embedding ----
    if (tid < NPG) s.noff[tid] = g_noff[nb + tid];
    else if (tid == NPG) s.noff[NPG] = g_noff[NN + g];
    if (tid < NPG) s.dinv[tid] = rsqrtf((float)(g_deg[nb + tid] + 1));  // +1 self loop
    if (tid < 64) s.h2t[tid * 129 + 128] = 0.f;     // pad sink rows (persist all layers)
    if (tid == NPG + 1) s.h4t[128] = 0.f;
    __syncthreads();
    const int cnt = s.noff[NPG];        // padded, multiple of 4
    const bool inS = (cnt <= CAP);

    if (inS) {   // coalesced 4B copy of padded edge list
        const unsigned int* gsrc = reinterpret_cast<const unsigned int*>(&g_esrc[g * SLOT]);
        unsigned int* dsts = reinterpret_cast<unsigned int*>(s.esrc);
        for (int i = tid; i < (cnt >> 2); i += NT) dsts[i] = gsrc[i];
    }
    for (int idx = tid; idx < NPG * 16; idx += NT) {
        int n = idx >> 4, q = idx & 15;
        float4 v = *reinterpret_cast<const float4*>(&z_table[__ldg(&z[nb + n]) * 64 + 4 * q]);
        *reinterpret_cast<float4*>(&s.xc[n * SXC + 128 + 4 * q]) = v;
    }
    __syncthreads();

    // ---- GEMM: h2t[c][r] = (xin @ W)[r][c] * dinv[r]  (4 rows x 4 cols / thread) ----
    auto gemm = [&](const float* xin, const float* Wg) {
        for (int i = tid; i < 1024; i += NT)
            *reinterpret_cast<float4*>(&s.Wsh[4 * i]) =
                *reinterpret_cast<const float4*>(&Wg[4 * i]);
        __syncthreads();
        const int c0 = (tid & 15) * 4;     // 4 contiguous cols
        const int r0 = (tid >> 4) * 4;     // 4 rows
        float acc[4][4];
        #pragma unroll
        for (int i = 0; i < 4; i++)
            #pragma unroll
            for (int j = 0; j < 4; j++) acc[i][j] = 0.f;
        #pragma unroll 4
        for (int kk = 0; kk < 16; kk++) {
            float4 xv[4];
            #pragma unroll
            for (int i = 0; i < 4; i++)
                xv[i] = *reinterpret_cast<const float4*>(&xin[(r0 + i) * SXC + 4 * kk]);
            #pragma unroll
            for (int kq = 0; kq < 4; kq++) {
                float4 wv = *reinterpret_cast<const float4*>(&s.Wsh[(4 * kk + kq) * 64 + c0]);
                float xs[4] = { (&xv[0].x)[kq], (&xv[1].x)[kq], (&xv[2].x)[kq], (&xv[3].x)[kq] };
                #pragma unroll
                for (int i = 0; i < 4; i++) {
                    acc[i][0] += xs[i] * wv.x;
                    acc[i][1] += xs[i] * wv.y;
                    acc[i][2] += xs[i] * wv.z;
                    acc[i][3] += xs[i] * wv.w;
                }
            }
        }
        #pragma unroll
        for (int i = 0; i < 4; i++) {
            float dv = s.dinv[r0 + i];
            #pragma unroll
            for (int j = 0; j < 4; j++)
                s.h2t[(c0 + j) * 129 + r0 + i] = acc[i][j] * dv;
        }
        __syncthreads();
    };

    // ---- gather + tanh: c = tid&63, 16 dst per thread; quad index loads ----
    auto gather = [&](int outbase) {
        const int c = tid & 63;
        const int dg = tid >> 6;           // 0..7, 16 dst each
        const float* hr = &s.h2t[c * 129];
        const float bc = s.bsh[c];
        const unsigned int* eq = reinterpret_cast<const unsigned int*>(s.esrc);
        const unsigned int* geq = reinterpret_cast<const unsigned int*>(&g_esrc[g * SLOT]);
        #pragma unroll 2
        for (int dd = 0; dd < 16; dd++) {
            int d = dg * 16 + dd;
            float sum = hr[d];                      // self loop
            int q0 = s.noff[d] >> 2, q1 = s.noff[d + 1] >> 2;
            if (inS) {
                for (int q = q0; q < q1; q++) {
                    unsigned int u = eq[q];
                    sum += hr[u & 255] + hr[(u >> 8) & 255]
                         + hr[(u >> 16) & 255] + hr[u >> 24];
                }
            } else {
                for (int q = q0; q < q1; q++) {
                    unsigned int u = geq[q];
                    sum += hr[u & 255] + hr[(u >> 8) & 255]
                         + hr[(u >> 16) & 255] + hr[u >> 24];
                }
            }
            s.xc[d * SXC + outbase + c] = tanhf(s.dinv[d] * sum + bc);
        }
        __syncthreads();
    };

    if (tid < 64) s.bsh[tid] = b0[tid];
    gemm(&s.xc[128], W0);       gather(0);    // layer 1: input = staged embedding
    if (tid < 64) s.bsh[tid] = b1[tid];
    gemm(&s.xc[0], W1);         gather(64);
    if (tid < 64) s.bsh[tid] = b2[tid];
    gemm(&s.xc[64], W2);        gather(128);  // overwrites embedding staging

    // ---- layer 4: 64 -> 1 ----
    if (tid < 64) s.bsh[tid] = W3[tid];
    __syncthreads();
    if (tid < 128) {
        float sum = 0.f;
        #pragma unroll
        for (int kq = 0; kq < 16; kq++) {
            float4 xv = *reinterpret_cast<const float4*>(&s.xc[tid * SXC + 128 + 4 * kq]);
            sum += xv.x * s.bsh[4 * kq] + xv.y * s.bsh[4 * kq + 1]
                 + xv.z * s.bsh[4 * kq + 2] + xv.w * s.bsh[4 * kq + 3];
        }
        s.h4t[tid] = sum * s.dinv[tid];
    }
    __syncthreads();
    if (tid < 128) {
        int d = tid;
        float sum = s.h4t[d];
        int q0 = s.noff[d] >> 2, q1 = s.noff[d + 1] >> 2;
        const unsigned int* eq = reinterpret_cast<const unsigned int*>(s.esrc);
        const unsigned int* geq = reinterpret_cast<const unsigned int*>(&g_esrc[g * SLOT]);
        if (inS) {
            for (int q = q0; q < q1; q++) {
                unsigned int u = eq[q];
                sum += s.h4t[u & 255] + s.h4t[(u >> 8) & 255]
                     + s.h4t[(u >> 16) & 255] + s.h4t[u >> 24];
            }
        } else {
            for (int q = q0; q < q1; q++) {
                unsigned int u = geq[q];
                sum += s.h4t[u & 255] + s.h4t[(u >> 8) & 255]
                     + s.h4t[(u >> 16) & 255] + s.h4t[u >> 24];
            }
        }
        float v = tanhf(s.dinv[d] * sum + b3[0]);
        s.keyv[d] = v;
        s.xc[d * SXC + 192] = v;
    }
    __syncthreads();

    // ---- sort-pool: stable descending rank; keep top KK ----
    if (tid < 128) {
        float ki = s.keyv[tid];
        int r = 0;
        for (int j = 0; j < 128; j++) {
            float kj = s.keyv[j];
            r += (kj > ki) || (kj == ki && j < tid);
        }
        if (r < KK) s.sel[r] = tid;
    }
    __syncthreads();

    // ---- conv1: per-node linear D->16, relu ----
    for (int i = tid; i < 16 * DD; i += NT) s.Wsh[i] = c1w[i];
    __syncthreads();
    if (tid < 16 * KK) {
        int c = tid & 15, k2 = tid >> 4;
        const float* row = &s.xc[s.sel[k2] * SXC];
        const float* wr = &s.Wsh[c * DD];
        float sum = __ldg(&c1b[c]);
        for (int d2 = 0; d2 < DD; d2++) sum += row[d2] * wr[d2];
        s.h1c[c * KK + k2] = fmaxf(sum, 0.f);
    }
    __syncthreads();

    // ---- maxpool(2,2) + stage conv2_w ----
    if (tid < 240) {
        int c = tid / 15, t2 = tid % 15;
        s.pool[c * 16 + t2] = fmaxf(s.h1c[c * KK + 2 * t2], s.h1c[c * KK + 2 * t2 + 1]);
    }
    for (int i = tid; i < 2560; i += NT) s.Wsh[i] = c2w[i];
    __syncthreads();

    // ---- conv2: 16ch x len15, k=5 -> 32ch x len11, relu ----
    if (tid < 352) {
        int o = tid / 11, t2 = tid % 11;
        float sum = __ldg(&c2b[o]);
        const float* wr = &s.Wsh[o * 80];
        #pragma unroll
        for (int i3 = 0; i3 < 16; i3++)
            #pragma unroll
            for (int j3 = 0; j3 < 5; j3++)
                sum += s.pool[i3 * 16 + t2 + j3] * wr[i3 * 5 + j3];
        s.c2o[tid] = fmaxf(sum, 0.f);
    }
    __syncthreads();

    // ---- lin1 (352->128, relu), 4-way f-split ----
    {
        int m = tid & 127, q = tid >> 7;
        int f0 = q * 88;
        float sum = 0.f;
        for (int f = f0; f < f0 + 88; f++) sum += s.c2o[f] * __ldg(&l1w[f * 128 + m]);
        s.partial[tid] = sum;
    }
    __syncthreads();
    if (tid < 128)
        s.hm[tid] = fmaxf(s.partial[tid] + s.partial[tid + 128] + s.partial[tid + 256]
                          + s.partial[tid + 384] + __ldg(&l1b[tid]), 0.f);
    __syncthreads();

    // ---- lin2 (128->1) ----
    if (tid < 32) {
        float sum = 0.f;
        #pragma unroll
        for (int q = 0; q < 4; q++) {
            int m = tid + 32 * q;
            sum += s.hm[m] * __ldg(&l2w[m]);
        }
        for (int o = 16; o; o >>= 1) sum += __shfl_down_sync(0xffffffffu, sum, o);
        if (tid == 0) out[g] = sum + __ldg(&l2b[0]);
    }

    // ---- reset counters for next replay (zero-init covers the first call) ----
    if (tid < NPG) { g_deg[nb + tid] = 0; g_cur[nb + tid] = 0; }
}

// ---------------- launch: 4 kernels; k_main is the 4th (ncu captures it) ---------
extern "C" void kernel_launch(void* const* d_in, const int* in_sizes, int n_in,
                              void* d_out, int out_size) {
    const int*   z   = (const int*)d_in[0];
    const int*   ei  = (const int*)d_in[1];
    const float* zt  = (const float*)d_in[3];
    const float* W0  = (const float*)d_in[4];
    const float* b0  = (const float*)d_in[5];
    const float* W1  = (const float*)d_in[6];
    const float* b1  = (const float*)d_in[7];
    const float* W2  = (const float*)d_in[8];
    const float* b2  = (const float*)d_in[9];
    const float* W3  = (const float*)d_in[10];
    const float* b3  = (const float*)d_in[11];
    const float* c1w = (const float*)d_in[12];
    const float* c1b = (const float*)d_in[13];
    const float* c2w = (const float*)d_in[14];
    const float* c2b = (const float*)d_in[15];
    const float* l1w = (const float*)d_in[16];
    const float* l1b = (const float*)d_in[17];
    const float* l2w = (const float*)d_in[18];
    const float* l2b = (const float*)d_in[19];
    float* out = (float*)d_out;

    const int* src = ei;
    const int* dst = ei + EE;

    k_count<<<EE / 256, 256>>>(dst);
    k_noff2<<<GG, 128>>>();
    k_scatter<<<EE / 256, 256>>>(src, dst);

    static_assert(sizeof(SmemD) <= 232448, "smem too large");
    cudaFuncSetAttribute(k_main, cudaFuncAttributeMaxDynamicSharedMemorySize,
                         (int)sizeof(SmemD));
    k_main<<<GG, NT, sizeof(SmemD)>>>(z, zt, W0, b0, W1, b1, W2, b2, W3, b3,
                                      c1w, c1b, c2w, c2b, l1w, l1b, l2w, l2b, out);
}

// round 8
// speedup vs baseline: 1.9405x; 1.2269x over previous
#include <cuda_runtime.h>
#include <math.h>

#define NN    131072
#define GG    1024
#define NPG   128
#define EE    2097152
#define KK    30
#define DD    193
#define CAP   3072
#define SLOT  8192          // per-graph padded edge slot (bytes), 4-aligned
#define SXC   196           // xc row stride (words, multiple of 4)
#define H2S   68            // h2t row stride (words, multiple of 4)
#define H2B   272           // h2t row stride bytes

// ---------------- scratch (static device globals; zero-initialized) ----------------
__device__ int g_deg[NN];                 // real in-degree (zeroed by k_main tail)
__device__ int g_cur[NN];                 // scatter cursors (zeroed by k_main tail)
__device__ int g_noff[NN + GG];           // padded local offsets; [NN+g] = padded total
__device__ unsigned char g_esrc[GG * SLOT];

union F2U { float2 f; unsigned long long u; };

__device__ __forceinline__ unsigned long long addf2(unsigned long long a,
                                                    unsigned long long b) {
    unsigned long long c;
    asm("add.rn.f32x2 %0, %1, %2;" : "=l"(c) : "l"(a), "l"(b));
    return c;
}

// ---------------- preprocessing (3 kernels; k_main is the 4th launch) -------------
__global__ void k_count(const int* __restrict__ dst) {
    int e = blockIdx.x * blockDim.x + threadIdx.x;
    if (e < EE) atomicAdd(&g_deg[dst[e]], 1);
}

__global__ void k_noff2() {   // per-graph scan of PADDED degrees + sentinel fill
    int g = blockIdx.x, i = threadIdx.x;
    int lane = i & 31, w = i >> 5;
    int deg = g_deg[g * NPG + i];
    int pdeg = (deg + 3) & ~3;
    int x = pdeg;
    for (int o = 1; o < 32; o <<= 1) {
        int t = __shfl_up_sync(0xffffffffu, x, o);
        if (lane >= o) x += t;
    }
    __shared__ int ws[4], wb[4];
    if (lane == 31) ws[w] = x;
    __syncthreads();
    if (i == 0) {
        int a = 0;
        for (int q = 0; q < 4; q++) { wb[q] = a; a += ws[q]; }
        g_noff[NN + g] = a;               // padded total
    }
    __syncthreads();
    int off = wb[w] + x - pdeg;           // exclusive padded offset
    g_noff[g * NPG + i] = off;
    // pad sentinels (index 128 -> h2t row 128 == 0)
    unsigned char* slot = &g_esrc[g * SLOT];
    for (int q = deg; q < pdeg; q++) slot[off + q] = 128;
}

__global__ void k_scatter(const int* __restrict__ src, const int* __restrict__ dst) {
    int e = blockIdx.x * blockDim.x + threadIdx.x;
    if (e < EE) {
        int d = dst[e];
        int pos = g_noff[d] + atomicAdd(&g_cur[d], 1);
        g_esrc[(d >> 7) * SLOT + pos] = (unsigned char)(src[e] & 127);
    }
}

// ---------------- main fused per-graph kernel ----------------
struct SmemD {
    float xc[NPG * SXC];     // concat(x1,x2,x3,x4); cols 128..191 stage embedding pre-L3
    float h2t[129 * H2S];    // (h @ W)*dinv, NODE-major, stride 68; row 128 == 0 (pad sink)
    float Wsh[4096];         // weight staging (reused for conv1_w / conv2_w)
    float dinv[NPG];
    float keyv[NPG];
    float bsh[64];           // bias (or W3)
    float h4t[132];          // [128] == 0 (pad sink)
    float partial[512];
    float h1c[16 * KK];
    float pool[16 * 16];
    float c2o[352];
    float hm[128];
    unsigned int eoff[CAP];  // per-edge byte offsets (idx * H2B); 16B-aligned here
    int   noff[NPG + 1];     // padded LOCAL offsets; noff[128] = padded count
    int   sel[KK];
    unsigned char esrc[CAP]; // raw byte indices (for layer-4 gather)
};

#define NT 512

__global__ __launch_bounds__(NT, 1) void k_main(
    const int* __restrict__ z, const float* __restrict__ z_table,
    const float* __restrict__ W0, const float* __restrict__ b0,
    const float* __restrict__ W1, const float* __restrict__ b1,
    const float* __restrict__ W2, const float* __restrict__ b2,
    const float* __restrict__ W3, const float* __restrict__ b3,
    const float* __restrict__ c1w, const float* __restrict__ c1b,
    const float* __restrict__ c2w, const float* __restrict__ c2b,
    const float* __restrict__ l1w, const float* __restrict__ l1b,
    const float* __restrict__ l2w, const float* __restrict__ l2b,
    float* __restrict__ out)
{
    extern __shared__ unsigned char smraw[];
    SmemD& s = *reinterpret_cast<SmemD*>(smraw);
    const int tid = threadIdx.x;
    const int g = blockIdx.x;
    const int nb = g * NPG;

    // ---- init: offsets, degrees, pad sinks, edge copy + offset expansion, embedding ----
    if (tid < NPG) s.noff[tid] = g_noff[nb + tid];
    else if (tid == NPG) s.noff[NPG] = g_noff[NN + g];
    if (tid < NPG) s.dinv[tid] = rsqrtf((float)(g_deg[nb + tid] + 1));  // +1 self loop
    if (tid < H2S) s.h2t[128 * H2S + tid] = 0.f;   // pad sink row (persists all layers)
    if (tid == NPG + 1) s.h4t[128] = 0.f;
    __syncthreads();
    const int cnt = s.noff[NPG];        // padded, multiple of 4
    const bool inS = (cnt <= CAP);

    if (inS) {   // copy padded edge bytes + expand to byte offsets (idx * 272)
        const unsigned int* gsrc = reinterpret_cast<const unsigned int*>(&g_esrc[g * SLOT]);
        unsigned int* dstb = reinterpret_cast<unsigned int*>(s.esrc);
        uint4* dsto = reinterpret_cast<uint4*>(s.eoff);
        for (int i = tid; i < (cnt >> 2); i += NT) {
            unsigned int u = gsrc[i];
            dstb[i] = u;
            uint4 o;
            o.x = (u & 255u) * H2B;
            o.y = ((u >> 8) & 255u) * H2B;
            o.z = ((u >> 16) & 255u) * H2B;
            o.w = (u >> 24) * H2B;
            dsto[i] = o;
        }
    }
    for (int idx = tid; idx < NPG * 16; idx += NT) {
        int n = idx >> 4, q = idx & 15;
        float4 v = *reinterpret_cast<const float4*>(&z_table[__ldg(&z[nb + n]) * 64 + 4 * q]);
        *reinterpret_cast<float4*>(&s.xc[n * SXC + 128 + 4 * q]) = v;
    }
    __syncthreads();

    // ---- GEMM: h2t[r][c] = (xin @ W)[r][c] * dinv[r]  (4 rows x 4 cols / thread) ----
    auto gemm = [&](const float* xin, const float* Wg) {
        for (int i = tid; i < 1024; i += NT)
            *reinterpret_cast<float4*>(&s.Wsh[4 * i]) =
                *reinterpret_cast<const float4*>(&Wg[4 * i]);
        __syncthreads();
        const int c0 = (tid & 15) * 4;     // 4 contiguous cols
        const int r0 = (tid >> 4) * 4;     // 4 rows
        float acc[4][4];
        #pragma unroll
        for (int i = 0; i < 4; i++)
            #pragma unroll
            for (int j = 0; j < 4; j++) acc[i][j] = 0.f;
        #pragma unroll 4
        for (int kk = 0; kk < 16; kk++) {
            float4 xv[4];
            #pragma unroll
            for (int i = 0; i < 4; i++)
                xv[i] = *reinterpret_cast<const float4*>(&xin[(r0 + i) * SXC + 4 * kk]);
            #pragma unroll
            for (int kq = 0; kq < 4; kq++) {
                float4 wv = *reinterpret_cast<const float4*>(&s.Wsh[(4 * kk + kq) * 64 + c0]);
                float xs[4] = { (&xv[0].x)[kq], (&xv[1].x)[kq], (&xv[2].x)[kq], (&xv[3].x)[kq] };
                #pragma unroll
                for (int i = 0; i < 4; i++) {
                    acc[i][0] += xs[i] * wv.x;
                    acc[i][1] += xs[i] * wv.y;
                    acc[i][2] += xs[i] * wv.z;
                    acc[i][3] += xs[i] * wv.w;
                }
            }
        }
        #pragma unroll
        for (int i = 0; i < 4; i++) {
            float dv = s.dinv[r0 + i];
            *reinterpret_cast<float4*>(&s.h2t[(r0 + i) * H2S + c0]) =
                make_float4(acc[i][0] * dv, acc[i][1] * dv, acc[i][2] * dv, acc[i][3] * dv);
        }
        __syncthreads();
    };

    // ---- gather + tanh: warp = one dst, lane = 2 channels; LDS.64 + add.f32x2 ----
    auto gather = [&](int outbase) {
        const int lane = tid & 31;
        const int w = tid >> 5;            // 16 warps, 8 dst each
        const char* h2b = reinterpret_cast<const char*>(s.h2t) + 8 * lane;
        const float2 bc = *reinterpret_cast<const float2*>(&s.bsh[2 * lane]);
        for (int dd = 0; dd < 8; dd++) {
            int d = w * 8 + dd;
            unsigned long long a0 =
                *reinterpret_cast<const unsigned long long*>(h2b + d * H2B);  // self loop
            unsigned long long a1 = 0ull, a2 = 0ull, a3 = 0ull;
            int q0 = s.noff[d] >> 2, q1 = s.noff[d + 1] >> 2;
            if (inS) {
                const uint4* oq = reinterpret_cast<const uint4*>(s.eoff);
                for (int q = q0; q < q1; q++) {
                    uint4 o = oq[q];
                    a0 = addf2(a0, *reinterpret_cast<const unsigned long long*>(h2b + o.x));
                    a1 = addf2(a1, *reinterpret_cast<const unsigned long long*>(h2b + o.y));
                    a2 = addf2(a2, *reinterpret_cast<const unsigned long long*>(h2b + o.z));
                    a3 = addf2(a3, *reinterpret_cast<const unsigned long long*>(h2b + o.w));
                }
            } else {
                const unsigned int* geq =
                    reinterpret_cast<const unsigned int*>(&g_esrc[g * SLOT]);
                for (int q = q0; q < q1; q++) {
                    unsigned int u = geq[q];
                    a0 = addf2(a0, *reinterpret_cast<const unsigned long long*>(
                                       h2b + (u & 255u) * H2B));
                    a1 = addf2(a1, *reinterpret_cast<const unsigned long long*>(
                                       h2b + ((u >> 8) & 255u) * H2B));
                    a2 = addf2(a2, *reinterpret_cast<const unsigned long long*>(
                                       h2b + ((u >> 16) & 255u) * H2B));
                    a3 = addf2(a3, *reinterpret_cast<const unsigned long long*>(
                                       h2b + (u >> 24) * H2B));
                }
            }
            F2U r; r.u = addf2(addf2(a0, a1), addf2(a2, a3));
            float dv = s.dinv[d];
            float2 o;
            o.x = tanhf(dv * r.f.x + bc.x);
            o.y = tanhf(dv * r.f.y + bc.y);
            *reinterpret_cast<float2*>(&s.xc[d * SXC + outbase + 2 * lane]) = o;
        }
        __syncthreads();
    };

    if (tid < 64) s.bsh[tid] = b0[tid];
    gemm(&s.xc[128], W0);       gather(0);    // layer 1: input = staged embedding
    if (tid < 64) s.bsh[tid] = b1[tid];
    gemm(&s.xc[0], W1);         gather(64);
    if (tid < 64) s.bsh[tid] = b2[tid];
    gemm(&s.xc[64], W2);        gather(128);  // overwrites embedding staging

    // ---- layer 4: 64 -> 1 ----
    if (tid < 64) s.bsh[tid] = W3[tid];
    __syncthreads();
    if (tid < 128) {
        float sum = 0.f;
        #pragma unroll
        for (int kq = 0; kq < 16; kq++) {
            float4 xv = *reinterpret_cast<const float4*>(&s.xc[tid * SXC + 128 + 4 * kq]);
            sum += xv.x * s.bsh[4 * kq] + xv.y * s.bsh[4 * kq + 1]
                 + xv.z * s.bsh[4 * kq + 2] + xv.w * s.bsh[4 * kq + 3];
        }
        s.h4t[tid] = sum * s.dinv[tid];
    }
    __syncthreads();
    if (tid < 128) {
        int d = tid;
        float s0 = s.h4t[d], s1 = 0.f, s2 = 0.f, s3 = 0.f;
        int q0 = s.noff[d] >> 2, q1 = s.noff[d + 1] >> 2;
        const unsigned int* eq = inS
            ? reinterpret_cast<const unsigned int*>(s.esrc)
            : reinterpret_cast<const unsigned int*>(&g_esrc[g * SLOT]);
        for (int q = q0; q < q1; q++) {
            unsigned int u = eq[q];
            s0 += s.h4t[u & 255u];
            s1 += s.h4t[(u >> 8) & 255u];
            s2 += s.h4t[(u >> 16) & 255u];
            s3 += s.h4t[u >> 24];
        }
        float sum = (s0 + s1) + (s2 + s3);
        float v = tanhf(s.dinv[d] * sum + b3[0]);
        s.keyv[d] = v;
        s.xc[d * SXC + 192] = v;
    }
    __syncthreads();

    // ---- sort-pool: stable descending rank; keep top KK ----
    if (tid < 128) {
        float ki = s.keyv[tid];
        int r = 0;
        for (int j = 0; j < 128; j++) {
            float kj = s.keyv[j];
            r += (kj > ki) || (kj == ki && j < tid);
        }
        if (r < KK) s.sel[r] = tid;
    }
    __syncthreads();

    // ---- conv1: per-node linear D->16, relu ----
    for (int i = tid; i < 16 * DD; i += NT) s.Wsh[i] = c1w[i];
    __syncthreads();
    if (tid < 16 * KK) {
        int c = tid & 15, k2 = tid >> 4;
        const float* row = &s.xc[s.sel[k2] * SXC];
        const float* wr = &s.Wsh[c * DD];
        float sum = __ldg(&c1b[c]);
        for (int d2 = 0; d2 < DD; d2++) sum += row[d2] * wr[d2];
        s.h1c[c * KK + k2] = fmaxf(sum, 0.f);
    }
    __syncthreads();

    // ---- maxpool(2,2) + stage conv2_w ----
    if (tid < 240) {
        int c = tid / 15, t2 = tid % 15;
        s.pool[c * 16 + t2] = fmaxf(s.h1c[c * KK + 2 * t2], s.h1c[c * KK + 2 * t2 + 1]);
    }
    for (int i = tid; i < 2560; i += NT) s.Wsh[i] = c2w[i];
    __syncthreads();

    // ---- conv2: 16ch x len15, k=5 -> 32ch x len11, relu ----
    if (tid < 352) {
        int o = tid / 11, t2 = tid % 11;
        float sum = __ldg(&c2b[o]);
        const float* wr = &s.Wsh[o * 80];
        #pragma unroll
        for (int i3 = 0; i3 < 16; i3++)
            #pragma unroll
            for (int j3 = 0; j3 < 5; j3++)
                sum += s.pool[i3 * 16 + t2 + j3] * wr[i3 * 5 + j3];
        s.c2o[tid] = fmaxf(sum, 0.f);
    }
    __syncthreads();

    // ---- lin1 (352->128, relu), 4-way f-split ----
    {
        int m = tid & 127, q = tid >> 7;
        int f0 = q * 88;
        float sum = 0.f;
        for (int f = f0; f < f0 + 88; f++) sum += s.c2o[f] * __ldg(&l1w[f * 128 + m]);
        s.partial[tid] = sum;
    }
    __syncthreads();
    if (tid < 128)
        s.hm[tid] = fmaxf(s.partial[tid] + s.partial[tid + 128] + s.partial[tid + 256]
                          + s.partial[tid + 384] + __ldg(&l1b[tid]), 0.f);
    __syncthreads();

    // ---- lin2 (128->1) ----
    if (tid < 32) {
        float sum = 0.f;
        #pragma unroll
        for (int q = 0; q < 4; q++) {
            int m = tid + 32 * q;
            sum += s.hm[m] * __ldg(&l2w[m]);
        }
        for (int o = 16; o; o >>= 1) sum += __shfl_down_sync(0xffffffffu, sum, o);
        if (tid == 0) out[g] = sum + __ldg(&l2b[0]);
    }

    // ---- reset counters for next replay (zero-init covers the first call) ----
    if (tid < NPG) { g_deg[nb + tid] = 0; g_cur[nb + tid] = 0; }
}

// ---------------- launch: 4 kernels; k_main is the 4th (ncu captures it) ---------
extern "C" void kernel_launch(void* const* d_in, const int* in_sizes, int n_in,
                              void* d_out, int out_size) {
    const int*   z   = (const int*)d_in[0];
    const int*   ei  = (const int*)d_in[1];
    const float* zt  = (const float*)d_in[3];
    const float* W0  = (const float*)d_in[4];
    const float* b0  = (const float*)d_in[5];
    const float* W1  = (const float*)d_in[6];
    const float* b1  = (const float*)d_in[7];
    const float* W2  = (const float*)d_in[8];
    const float* b2  = (const float*)d_in[9];
    const float* W3  = (const float*)d_in[10];
    const float* b3  = (const float*)d_in[11];
    const float* c1w = (const float*)d_in[12];
    const float* c1b = (const float*)d_in[13];
    const float* c2w = (const float*)d_in[14];
    const float* c2b = (const float*)d_in[15];
    const float* l1w = (const float*)d_in[16];
    const float* l1b = (const float*)d_in[17];
    const float* l2w = (const float*)d_in[18];
    const float* l2b = (const float*)d_in[19];
    float* out = (float*)d_out;

    const int* src = ei;
    const int* dst = ei + EE;

    k_count<<<EE / 256, 256>>>(dst);
    k_noff2<<<GG, 128>>>();
    k_scatter<<<EE / 256, 256>>>(src, dst);

    static_assert(sizeof(SmemD) <= 232448, "smem too large");
    cudaFuncSetAttribute(k_main, cudaFuncAttributeMaxDynamicSharedMemorySize,
                         (int)sizeof(SmemD));
    k_main<<<GG, NT, sizeof(SmemD)>>>(z, zt, W0, b0, W1, b1, W2, b2, W3, b3,
                                      c1w, c1b, c2w, c2b, l1w, l1b, l2w, l2b, out);
}